// round 9
// baseline (speedup 1.0000x reference)
#include <cuda_runtime.h>

// Fused masked-scale MSE, round 9:
//   R8 (v8 256-bit loads, grid 2048x256, ticket finish — kernel 41.38us,
//   DRAM 83.3%) with ONE change: exact trip count (8 iters/thread on this
//   shape) with carried pointer increments — no bounds predicate, no
//   per-iteration IMAD.WIDE address recompute. Generic tail kept for other
//   shapes but not taken here.

__device__ float        g_partial = 0.0f;
__device__ unsigned int g_ticket  = 0u;

struct f8 { float a, b, c, d, e, f, g, h; };

__device__ __forceinline__ f8 ldg256(const float* p) {
    f8 v;
    asm("ld.global.v8.f32 {%0,%1,%2,%3,%4,%5,%6,%7}, [%8];"
        : "=f"(v.a), "=f"(v.b), "=f"(v.c), "=f"(v.d),
          "=f"(v.e), "=f"(v.f), "=f"(v.g), "=f"(v.h)
        : "l"(p));
    return v;
}

__device__ __forceinline__ float elem_term(float n, float l) {
    // labels are exactly 0.0f, 1.0f, or 2.0f
    float sn = (l == 1.0f) ? 10.0f : ((l == 2.0f) ? 5.0f : 1.0f);
    float sl = (l == 0.0f) ? 1.0f : 10.0f;
    float d = fmaf(n, sn, -l * sl);
    return d * d;
}

__device__ __forceinline__ float acc_f8(float acc, const f8& a, const f8& b) {
    acc += elem_term(a.a, b.a);
    acc += elem_term(a.b, b.b);
    acc += elem_term(a.c, b.c);
    acc += elem_term(a.d, b.d);
    acc += elem_term(a.e, b.e);
    acc += elem_term(a.f, b.f);
    acc += elem_term(a.g, b.g);
    acc += elem_term(a.h, b.h);
    return acc;
}

__global__ void __launch_bounds__(256)
mse_loss_kernel(const float* __restrict__ norms,
                const float* __restrict__ labels,
                float* __restrict__ out,
                int n_vec8,       // number of 8-float groups
                int per_thread,   // exact iterations per thread
                float inv_n)
{
    const int tid = blockIdx.x * blockDim.x + threadIdx.x;
    const int stride = gridDim.x * blockDim.x;   // in 8-float groups

    const float* pn = norms  + (size_t)tid * 8;
    const float* pl = labels + (size_t)tid * 8;
    const size_t step = (size_t)stride * 8;

    float acc = 0.0f;

    // Counted loop, no bounds predicate: pointer-carried addressing.
    #pragma unroll 1
    for (int k = 0; k < per_thread; k++) {
        f8 a = ldg256(pn);
        f8 b = ldg256(pl);
        acc = acc_f8(acc, a, b);
        pn += step;
        pl += step;
    }

    // Generic tail (not taken on 4096x8192 with grid 2048x256).
    for (int i = tid + per_thread * stride; i < n_vec8; i += stride) {
        f8 a = ldg256(norms  + (size_t)i * 8);
        f8 b = ldg256(labels + (size_t)i * 8);
        acc = acc_f8(acc, a, b);
    }

    // warp reduction
    #pragma unroll
    for (int off = 16; off > 0; off >>= 1)
        acc += __shfl_down_sync(0xffffffffu, acc, off);

    __shared__ float warp_sums[8];
    int lane = threadIdx.x & 31;
    int wid  = threadIdx.x >> 5;
    if (lane == 0) warp_sums[wid] = acc;
    __syncthreads();

    if (wid == 0) {
        float v = (lane < (int)(blockDim.x >> 5)) ? warp_sums[lane] : 0.0f;
        #pragma unroll
        for (int off = 4; off > 0; off >>= 1)
            v += __shfl_down_sync(0xffffffffu, v, off);

        if (lane == 0) {
            atomicAdd(&g_partial, v);
            __threadfence();
            unsigned int ticket = atomicAdd(&g_ticket, 1u);
            if (ticket == gridDim.x - 1) {
                // all block partials visible; finish and reset for next replay
                out[0] = g_partial * inv_n;
                g_partial = 0.0f;
                g_ticket  = 0u;
            }
        }
    }
}

extern "C" void kernel_launch(void* const* d_in, const int* in_sizes, int n_in,
                              void* d_out, int out_size)
{
    const float* norms  = (const float*)d_in[0];
    const float* labels = (const float*)d_in[1];
    float* out = (float*)d_out;

    int n_elems = in_sizes[0];        // 33554432
    int n_vec8  = n_elems / 8;        // 4194304 (exact)
    float inv_n = 1.0f / (float)n_elems;

    const int threads = 256;
    const int blocks  = 2048;         // measured-best grid point
    int total = threads * blocks;
    int per_thread = n_vec8 / total;  // 8 on this shape

    mse_loss_kernel<<<blocks, threads>>>(norms, labels, out,
                                         n_vec8, per_thread, inv_n);
}